// round 6
// baseline (speedup 1.0000x reference)
#include <cuda_runtime.h>
#include <cuda_bf16.h>
#include <math.h>
#include <stdint.h>

// ---------------- problem constants ----------------
#define Bb   2
#define SS   2048
#define DD   1024
#define HH   16
#define HDIM 64
#define EE   4
#define KSEL 2
#define HIDD 4096
#define TT   (Bb*SS)   // 4096 tokens

// ---------------- fp32 scratch ----------------
static const size_t OFF_QKV   = 0;                                   // TT*3*DD
static const size_t OFF_X1    = OFF_QKV   + (size_t)TT*3*DD;         // TT*DD
static const size_t OFF_H2F   = OFF_X1    + (size_t)TT*DD;           // TT*DD
static const size_t OFF_SDOWN = OFF_H2F   + (size_t)TT*DD;           // TT*DD
static const size_t OFF_EO    = OFF_SDOWN + (size_t)TT*DD;           // EE*TT*DD
static const size_t OFF_PROBS = OFF_EO    + (size_t)EE*TT*DD;        // TT*EE
static const size_t OFF_TOPW  = OFF_PROBS + (size_t)TT*EE;           // TT*KSEL
static const size_t F_TOTAL   = OFF_TOPW  + (size_t)TT*KSEL;
__device__ float g_f[F_TOTAL];

// ---------------- bf16 hi/lo planes ----------------
static const size_t BO_WQKV = 0;                                 // 3*DD*DD
static const size_t BO_WO   = BO_WQKV + (size_t)3*DD*DD;         // DD*DD
static const size_t BO_WEUP = BO_WO   + (size_t)DD*DD;           // EE*HIDD*DD
static const size_t BO_WEDN = BO_WEUP + (size_t)EE*HIDD*DD;      // EE*DD*HIDD
static const size_t BO_WSUP = BO_WEDN + (size_t)EE*DD*HIDD;      // HIDD*DD
static const size_t BO_WSDN = BO_WSUP + (size_t)HIDD*DD;         // DD*HIDD
static const size_t BO_H    = BO_WSDN + (size_t)DD*HIDD;         // TT*DD
static const size_t BO_ATTN = BO_H    + (size_t)TT*DD;           // TT*DD
static const size_t BO_H2   = BO_ATTN + (size_t)TT*DD;           // TT*DD
static const size_t BO_SUP  = BO_H2   + (size_t)TT*DD;           // TT*HIDD
static const size_t BO_UPB  = BO_SUP  + (size_t)TT*HIDD;         // EE*TT*HIDD
static const size_t B_TOTAL = BO_UPB  + (size_t)EE*TT*HIDD;
__device__ __nv_bfloat16 g_bh[B_TOTAL];
__device__ __nv_bfloat16 g_bl[B_TOTAL];

// ---------------- int scratch ----------------
static const size_t IOFF_SLOT    = 0;                       // EE*TT
static const size_t IOFF_TOKSLOT = IOFF_SLOT + EE*TT;       // TT*KSEL
static const size_t IOFF_TOPI    = IOFF_TOKSLOT + TT*KSEL;  // TT*KSEL
static const size_t IOFF_CNT     = IOFF_TOPI + TT*KSEL;     // EE
__device__ int g_i[IOFF_CNT + EE];

// ---------------- helpers ----------------
__device__ __forceinline__ float gelu_tanh(float x) {
    float z = 0.7978845608028654f * (x + 0.044715f * x * x * x);
    float e = __expf(2.f * z);
    float th = 1.f - 2.f / (e + 1.f);
    return 0.5f * x * (1.f + th);
}

__device__ __forceinline__ void mma_bf16(float* d, const uint32_t* a, const uint32_t* b) {
    asm volatile(
        "mma.sync.aligned.m16n8k16.row.col.f32.bf16.bf16.f32 "
        "{%0,%1,%2,%3}, {%4,%5,%6,%7}, {%8,%9}, {%0,%1,%2,%3};\n"
        : "+f"(d[0]), "+f"(d[1]), "+f"(d[2]), "+f"(d[3])
        : "r"(a[0]), "r"(a[1]), "r"(a[2]), "r"(a[3]), "r"(b[0]), "r"(b[1]));
}

__device__ __forceinline__ void ldsm4(uint32_t* r, uint32_t addr) {
    asm volatile("ldmatrix.sync.aligned.m8n8.x4.shared.b16 {%0,%1,%2,%3}, [%4];"
                 : "=r"(r[0]), "=r"(r[1]), "=r"(r[2]), "=r"(r[3]) : "r"(addr));
}

__device__ __forceinline__ void split2(float x, float y, uint32_t& hi, uint32_t& lo) {
    __nv_bfloat16 hx = __float2bfloat16_rn(x);
    __nv_bfloat16 hy = __float2bfloat16_rn(y);
    __nv_bfloat16 lx = __float2bfloat16_rn(x - __bfloat162float(hx));
    __nv_bfloat16 ly = __float2bfloat16_rn(y - __bfloat162float(hy));
    __nv_bfloat162 h2 = __nv_bfloat162(hx, hy);
    __nv_bfloat162 l2 = __nv_bfloat162(lx, ly);
    hi = *reinterpret_cast<uint32_t*>(&h2);
    lo = *reinterpret_cast<uint32_t*>(&l2);
}

__device__ __forceinline__ void cpa16(uint32_t dst, const void* src, int srcbytes) {
    asm volatile("cp.async.cg.shared.global [%0], [%1], 16, %2;"
                 :: "r"(dst), "l"(src), "r"(srcbytes));
}
__device__ __forceinline__ void cpa_commit() { asm volatile("cp.async.commit_group;"); }
__device__ __forceinline__ void cpa_wait_all() { asm volatile("cp.async.wait_group 0;"); }

// ---------------- fp32 -> bf16 hi/lo convert ----------------
__global__ void conv_kernel(const float* __restrict__ in, __nv_bfloat16* __restrict__ hi,
                            __nv_bfloat16* __restrict__ lo, int n) {
    int i = (blockIdx.x * blockDim.x + threadIdx.x) * 4;
    if (i >= n) return;
    float4 v = *(const float4*)(in + i);
    uint32_t h0, l0, h1, l1;
    split2(v.x, v.y, h0, l0);
    split2(v.z, v.w, h1, l1);
    *(uint32_t*)(hi + i)     = h0;
    *(uint32_t*)(hi + i + 2) = h1;
    *(uint32_t*)(lo + i)     = l0;
    *(uint32_t*)(lo + i + 2) = l1;
}

// ---------------- LayerNorm (MODE0: bf16 planes only; MODE1: + fp32 out) ------
template <int MODE>
__global__ void ln_kernel(const float* __restrict__ x, const float* __restrict__ g,
                          const float* __restrict__ b, float* __restrict__ outf,
                          __nv_bfloat16* __restrict__ ohi, __nv_bfloat16* __restrict__ olo) {
    int t = blockIdx.x, tid = threadIdx.x;
    const float* xr = x + (size_t)t * DD;
    float v[4], s = 0.f, sq = 0.f;
#pragma unroll
    for (int k = 0; k < 4; k++) {
        v[k] = xr[tid + k * 256];
        s += v[k]; sq += v[k] * v[k];
    }
    __shared__ float rs[256], rq[256];
    rs[tid] = s; rq[tid] = sq;
    __syncthreads();
    for (int o = 128; o > 0; o >>= 1) {
        if (tid < o) { rs[tid] += rs[tid + o]; rq[tid] += rq[tid + o]; }
        __syncthreads();
    }
    float mean = rs[0] * (1.f / DD);
    float var  = rq[0] * (1.f / DD) - mean * mean;
    float inv  = rsqrtf(var + 1e-5f);
#pragma unroll
    for (int k = 0; k < 4; k++) {
        int d = tid + k * 256;
        float val = (v[k] - mean) * inv * g[d] + b[d];
        if (MODE == 1) outf[(size_t)t * DD + d] = val;
        __nv_bfloat16 hx = __float2bfloat16_rn(val);
        __nv_bfloat16 lx = __float2bfloat16_rn(val - __bfloat162float(hx));
        ohi[(size_t)t * DD + d] = hx;
        olo[(size_t)t * DD + d] = lx;
    }
}

// ---------------- tensor-core NT GEMM with split-bf16 planes ------------------
// C = A * B^T + bias; A,B given as bf16 hi/lo planes (row-major [rows, K]).
// Block 128x128, k-tile 32, 2-stage cp.async pipeline, 8 warps of 64x32.
// EPI: 0 fp32 out; 1 gelu -> bf16 hi/lo planes; 2 fp32 out + resid
#define LDAH 40   // smem row pitch (halves): 32 data + 8 pad
#define STAGE_B 40960      // bytes per stage (4 arrays * 10240)
#define ARR_B   10240
template <int EPI>
__global__ void __launch_bounds__(256) hgemm_nt(
    const __nv_bfloat16* __restrict__ Ahi, const __nv_bfloat16* __restrict__ Alo,
    const __nv_bfloat16* __restrict__ Bhi, const __nv_bfloat16* __restrict__ Blo,
    const float* __restrict__ bias, const float* __restrict__ resid,
    float* __restrict__ Cf, __nv_bfloat16* __restrict__ Chi, __nv_bfloat16* __restrict__ Clo,
    int M, int N, int Kd,
    const int* __restrict__ rowIdx, const int* __restrict__ cnt,
    size_t aZ, size_t bZ, size_t biasZ, size_t cZ, size_t idxZ) {
    int z = blockIdx.z;
    Ahi += (size_t)z * aZ; Alo += (size_t)z * aZ;
    Bhi += (size_t)z * bZ; Blo += (size_t)z * bZ;
    bias += (size_t)z * biasZ;
    if (EPI == 1) { Chi += (size_t)z * cZ; Clo += (size_t)z * cZ; }
    else          { Cf  += (size_t)z * cZ; }
    if (rowIdx) rowIdx += (size_t)z * idxZ;
    if (cnt) M = cnt[z];
    int mBase = blockIdx.y * 128;
    if (mBase >= M) return;
    int n0 = blockIdx.x * 128;

    extern __shared__ __align__(16) uint16_t smem_dyn[];
    uint32_t smemBase = (uint32_t)__cvta_generic_to_shared(smem_dyn);

    int tid = threadIdx.x;
    int wid = tid >> 5, lane = tid & 31;
    int warp_m = (wid >> 2) * 64;
    int warp_n = (wid & 3) * 32;

    // ---- cp.async source mapping: 2 segments/thread/array ----
    const __nv_bfloat16 *aHiSrc[2], *aLoSrc[2], *bHiSrc[2], *bLoSrc[2];
    int aSz[2];
    uint32_t sOff[2];
#pragma unroll
    for (int i = 0; i < 2; i++) {
        int seg = tid + i * 256;
        int row = seg >> 2;
        int kh  = (seg & 3) * 8;
        sOff[i] = (uint32_t)(row * LDAH + kh) * 2;
        int gmr = mBase + row;
        bool ok = gmr < M;
        int sr = ok ? (rowIdx ? rowIdx[gmr] : gmr) : 0;
        aHiSrc[i] = Ahi + (size_t)sr * Kd + kh;
        aLoSrc[i] = Alo + (size_t)sr * Kd + kh;
        aSz[i] = ok ? 16 : 0;
        int bn = n0 + row;
        bHiSrc[i] = Bhi + (size_t)bn * Kd + kh;
        bLoSrc[i] = Blo + (size_t)bn * Kd + kh;
    }

    // ---- ldmatrix offsets (within one array) ----
    uint32_t aOff[4];
#pragma unroll
    for (int mt = 0; mt < 4; mt++) {
        int row = warp_m + mt * 16 + (lane & 15);
        int colh = (lane >> 4) * 8;
        aOff[mt] = (uint32_t)(row * LDAH + colh) * 2;
    }
    uint32_t bOff[2];
#pragma unroll
    for (int np = 0; np < 2; np++) {
        int row = warp_n + np * 16 + (lane & 7) + ((lane >> 4) << 3);
        int colh = ((lane >> 3) & 1) * 8;
        bOff[np] = (uint32_t)(row * LDAH + colh) * 2;
    }

    float c[4][4][4];
#pragma unroll
    for (int i = 0; i < 4; i++)
#pragma unroll
        for (int j = 0; j < 4; j++)
#pragma unroll
            for (int k = 0; k < 4; k++) c[i][j][k] = 0.f;

    int nK = Kd >> 5;

    // prefetch stage 0
    {
        uint32_t sb = smemBase;
#pragma unroll
        for (int i = 0; i < 2; i++) {
            cpa16(sb + sOff[i],             aHiSrc[i], aSz[i]);
            cpa16(sb + ARR_B + sOff[i],     aLoSrc[i], aSz[i]);
            cpa16(sb + 2 * ARR_B + sOff[i], bHiSrc[i], 16);
            cpa16(sb + 3 * ARR_B + sOff[i], bLoSrc[i], 16);
        }
        cpa_commit();
    }

    for (int kt = 0; kt < nK; kt++) {
        int cur = kt & 1;
        cpa_wait_all();
        __syncthreads();
        if (kt + 1 < nK) {
            uint32_t sb = smemBase + (cur ^ 1) * STAGE_B;
            int koff = (kt + 1) * 32;
#pragma unroll
            for (int i = 0; i < 2; i++) {
                cpa16(sb + sOff[i],             aHiSrc[i] + koff, aSz[i]);
                cpa16(sb + ARR_B + sOff[i],     aLoSrc[i] + koff, aSz[i]);
                cpa16(sb + 2 * ARR_B + sOff[i], bHiSrc[i] + koff, 16);
                cpa16(sb + 3 * ARR_B + sOff[i], bLoSrc[i] + koff, 16);
            }
            cpa_commit();
        }
        uint32_t stageB = smemBase + cur * STAGE_B;
#pragma unroll
        for (int ks = 0; ks < 2; ks++) {
            uint32_t kb = ks * 32;
            uint32_t ah[4][4], al[4][4], bh[4][2], bl[4][2];
#pragma unroll
            for (int mt = 0; mt < 4; mt++) {
                ldsm4(ah[mt], stageB + aOff[mt] + kb);
                ldsm4(al[mt], stageB + ARR_B + aOff[mt] + kb);
            }
#pragma unroll
            for (int np = 0; np < 2; np++) {
                uint32_t r[4];
                ldsm4(r, stageB + 2 * ARR_B + bOff[np] + kb);
                bh[2 * np][0] = r[0]; bh[2 * np][1] = r[1];
                bh[2 * np + 1][0] = r[2]; bh[2 * np + 1][1] = r[3];
                ldsm4(r, stageB + 3 * ARR_B + bOff[np] + kb);
                bl[2 * np][0] = r[0]; bl[2 * np][1] = r[1];
                bl[2 * np + 1][0] = r[2]; bl[2 * np + 1][1] = r[3];
            }
#pragma unroll
            for (int mt = 0; mt < 4; mt++)
#pragma unroll
                for (int nt = 0; nt < 4; nt++) {
                    mma_bf16(c[mt][nt], ah[mt], bh[nt]);
                    mma_bf16(c[mt][nt], ah[mt], bl[nt]);
                    mma_bf16(c[mt][nt], al[mt], bh[nt]);
                }
        }
    }

    // ---- epilogue ----
#pragma unroll
    for (int mt = 0; mt < 4; mt++) {
#pragma unroll
        for (int nt = 0; nt < 4; nt++) {
            int col = n0 + warp_n + nt * 8 + (lane & 3) * 2;
            float2 bb = *(const float2*)(bias + col);
#pragma unroll
            for (int half = 0; half < 2; half++) {
                int r = mBase + warp_m + mt * 16 + (lane >> 2) + half * 8;
                if (r >= M) continue;
                float v0 = c[mt][nt][half * 2 + 0] + bb.x;
                float v1 = c[mt][nt][half * 2 + 1] + bb.y;
                if (EPI == 1) {
                    v0 = gelu_tanh(v0); v1 = gelu_tanh(v1);
                    uint32_t hi, lo;
                    split2(v0, v1, hi, lo);
                    *(uint32_t*)(Chi + (size_t)r * N + col) = hi;
                    *(uint32_t*)(Clo + (size_t)r * N + col) = lo;
                } else {
                    if (EPI == 2) {
                        float2 rr = *(const float2*)(resid + (size_t)r * N + col);
                        v0 += rr.x; v1 += rr.y;
                    }
                    *(float2*)(Cf + (size_t)r * N + col) = make_float2(v0, v1);
                }
            }
        }
    }
}

// ---------------- causal flash attention (bf16 hi/lo output) ------------------
__global__ void __launch_bounds__(512) attn_kernel(const float* __restrict__ qkv,
                                                   __nv_bfloat16* __restrict__ ohi,
                                                   __nv_bfloat16* __restrict__ olo) {
    __shared__ float q_s[16][64];
    __shared__ float k_s[32][65];
    __shared__ float v_s[32][64];
    int bh = blockIdx.y;
    int b = bh >> 4, h = bh & 15;
    int q0 = blockIdx.x * 16;
    int tid = threadIdx.x;
    int w = tid >> 5, lane = tid & 31;

    {
        int i = tid * 2;
        int qi = i >> 6, d = i & 63;
        const float* src = qkv + ((size_t)(b * SS + q0 + qi)) * (3 * DD) + h * 64 + d;
        float2 v = *(const float2*)src;
        q_s[qi][d]     = v.x * 0.125f;
        q_s[qi][d + 1] = v.y * 0.125f;
    }
    __syncthreads();
    float qr[64];
#pragma unroll
    for (int d = 0; d < 64; d++) qr[d] = q_s[w][d];

    int q = q0 + w;
    float M = -1e30f, L = 0.f, o0 = 0.f, o1 = 0.f;
    int nkeys = q0 + 16;

    for (int t0 = 0; t0 < nkeys; t0 += 32) {
        __syncthreads();
        {
            int r  = tid >> 4;
            int c4 = (tid & 15) * 4;
            int key = t0 + r;
            float4 kv = make_float4(0, 0, 0, 0), vv = make_float4(0, 0, 0, 0);
            if (key < SS) {
                size_t base = ((size_t)(b * SS + key)) * (3 * DD) + h * 64 + c4;
                kv = *(const float4*)(qkv + DD + base);
                vv = *(const float4*)(qkv + 2 * DD + base);
            }
            k_s[r][c4 + 0] = kv.x; k_s[r][c4 + 1] = kv.y;
            k_s[r][c4 + 2] = kv.z; k_s[r][c4 + 3] = kv.w;
            *(float4*)&v_s[r][c4] = vv;
        }
        __syncthreads();

        int key = t0 + lane;
        bool act = (key <= q);
        float s = -1e30f;
        if (act) {
            float a = 0.f;
#pragma unroll
            for (int d = 0; d < 64; d++) a += qr[d] * k_s[lane][d];
            s = a;
        }
        float mcur = s;
#pragma unroll
        for (int off = 16; off > 0; off >>= 1)
            mcur = fmaxf(mcur, __shfl_xor_sync(0xffffffffu, mcur, off));
        if (mcur > M) {
            float sc = __expf(M - mcur);
            o0 *= sc; o1 *= sc; L *= sc;
            M = mcur;
        }
        float p = act ? __expf(s - M) : 0.f;
        float ls = p;
#pragma unroll
        for (int off = 16; off > 0; off >>= 1)
            ls += __shfl_xor_sync(0xffffffffu, ls, off);
        L += ls;
#pragma unroll
        for (int j = 0; j < 32; j++) {
            float pj = __shfl_sync(0xffffffffu, p, j);
            float2 vv = *(const float2*)&v_s[j][lane * 2];
            o0 += pj * vv.x;
            o1 += pj * vv.y;
        }
    }
    float inv = 1.f / L;
    uint32_t hi, lo;
    split2(o0 * inv, o1 * inv, hi, lo);
    size_t off = ((size_t)(b * SS + q)) * DD + h * 64 + lane * 2;
    *(uint32_t*)(ohi + off) = hi;
    *(uint32_t*)(olo + off) = lo;
}

// ---------------- MoE router ----------------
__global__ void router_kernel(const float* __restrict__ h2, const float* __restrict__ Wg,
                              float* __restrict__ probs, float* __restrict__ topw,
                              int* __restrict__ topi, int* __restrict__ slot_tok,
                              int* __restrict__ tok_slot, int* __restrict__ cnt) {
    int t = blockIdx.x, tid = threadIdx.x;  // 128 threads
    const float* hr = h2 + (size_t)t * DD;
    float a0 = 0, a1 = 0, a2 = 0, a3 = 0;
    for (int d = tid; d < DD; d += 128) {
        float hv = hr[d];
        a0 += hv * Wg[d];
        a1 += hv * Wg[DD + d];
        a2 += hv * Wg[2 * DD + d];
        a3 += hv * Wg[3 * DD + d];
    }
    __shared__ float r[4][128];
    r[0][tid] = a0; r[1][tid] = a1; r[2][tid] = a2; r[3][tid] = a3;
    __syncthreads();
    for (int o = 64; o > 0; o >>= 1) {
        if (tid < o) {
#pragma unroll
            for (int e = 0; e < 4; e++) r[e][tid] += r[e][tid + o];
        }
        __syncthreads();
    }
    if (tid == 0) {
        float l[4] = {r[0][0], r[1][0], r[2][0], r[3][0]};
        float m = fmaxf(fmaxf(l[0], l[1]), fmaxf(l[2], l[3]));
        float p[4], sum = 0.f;
#pragma unroll
        for (int e = 0; e < 4; e++) { p[e] = __expf(l[e] - m); sum += p[e]; }
#pragma unroll
        for (int e = 0; e < 4; e++) { p[e] /= sum; probs[t * 4 + e] = p[e]; }
        int i0 = 0;
#pragma unroll
        for (int e = 1; e < 4; e++) if (p[e] > p[i0]) i0 = e;
        int i1 = -1;
#pragma unroll
        for (int e = 0; e < 4; e++)
            if (e != i0 && (i1 < 0 || p[e] > p[i1])) i1 = e;
        float w0 = p[i0], w1 = p[i1], ws = w0 + w1;
        w0 /= ws; w1 /= ws;
        int pos0 = atomicAdd(&cnt[i0], 1);
        slot_tok[i0 * TT + pos0] = t;
        tok_slot[t * 2]     = i0 * TT + pos0;
        int pos1 = atomicAdd(&cnt[i1], 1);
        slot_tok[i1 * TT + pos1] = t;
        tok_slot[t * 2 + 1] = i1 * TT + pos1;
        topw[t * 2] = w0; topw[t * 2 + 1] = w1;
        topi[t * 2] = i0; topi[t * 2 + 1] = i1;
    }
}

// ---------------- aux loss ----------------
__global__ void aux_kernel(const float* __restrict__ probs, const int* __restrict__ topi,
                           float* __restrict__ auxout) {
    int tid = threadIdx.x;  // 512
    float ps[4] = {0, 0, 0, 0};
    float cs[4] = {0, 0, 0, 0};
    for (int t = tid; t < TT; t += 512) {
#pragma unroll
        for (int e = 0; e < 4; e++) ps[e] += probs[t * 4 + e];
        cs[topi[t * 2]] += 1.f;
        cs[topi[t * 2 + 1]] += 1.f;
    }
    __shared__ float sp[4][512], sc[4][512];
#pragma unroll
    for (int e = 0; e < 4; e++) { sp[e][tid] = ps[e]; sc[e][tid] = cs[e]; }
    __syncthreads();
    for (int o = 256; o > 0; o >>= 1) {
        if (tid < o) {
#pragma unroll
            for (int e = 0; e < 4; e++) {
                sp[e][tid] += sp[e][tid + o];
                sc[e][tid] += sc[e][tid + o];
            }
        }
        __syncthreads();
    }
    if (tid == 0) {
        float aux = 0.f;
#pragma unroll
        for (int e = 0; e < 4; e++) {
            float fi = sc[e][0] / (float)(TT * KSEL);
            float Pi = sp[e][0] / (float)TT;
            aux += fi * Pi;
        }
        auxout[0] = 0.01f * (float)EE * aux;
    }
}

// ---------------- final combine (scalar stores) ----------------
__global__ void combine_kernel(const float* __restrict__ x1, const float* __restrict__ sdown,
                               const float* __restrict__ eo, const float* __restrict__ topw,
                               const int* __restrict__ tok_slot, float* __restrict__ xout) {
    int t = blockIdx.x, tid = threadIdx.x;
    int c = tid * 4;
    int s0 = tok_slot[t * 2], s1 = tok_slot[t * 2 + 1];
    float w0 = topw[t * 2], w1 = topw[t * 2 + 1];
    float4 a  = *(const float4*)(x1 + (size_t)t * DD + c);
    float4 sd = *(const float4*)(sdown + (size_t)t * DD + c);
    float4 e0 = *(const float4*)(eo + (size_t)s0 * DD + c);
    float4 e1 = *(const float4*)(eo + (size_t)s1 * DD + c);
    float* o = xout + (size_t)t * DD + c;
    o[0] = a.x + sd.x + w0 * e0.x + w1 * e1.x;
    o[1] = a.y + sd.y + w0 * e0.y + w1 * e1.y;
    o[2] = a.z + sd.z + w0 * e0.z + w1 * e1.z;
    o[3] = a.w + sd.w + w0 * e0.w + w1 * e1.w;
}

// ---------------- launch ------------------------------------------------------
#define SMEM_GEMM 81920

extern "C" void kernel_launch(void* const* d_in, const int* in_sizes, int n_in,
                              void* d_out, int out_size) {
    const float* x      = (const float*)d_in[0];
    const float* ln1_g  = (const float*)d_in[1];
    const float* ln1_b  = (const float*)d_in[2];
    const float* Wqkv   = (const float*)d_in[3];
    const float* bqkv   = (const float*)d_in[4];
    const float* Wo     = (const float*)d_in[5];
    const float* bo     = (const float*)d_in[6];
    const float* ln2_g  = (const float*)d_in[7];
    const float* ln2_b  = (const float*)d_in[8];
    const float* Wg     = (const float*)d_in[9];
    const float* We_up  = (const float*)d_in[10];
    const float* be_up  = (const float*)d_in[11];
    const float* We_dn  = (const float*)d_in[12];
    const float* be_dn  = (const float*)d_in[13];
    const float* Ws_up  = (const float*)d_in[14];
    const float* bs_up  = (const float*)d_in[15];
    const float* Ws_dn  = (const float*)d_in[16];
    const float* bs_dn  = (const float*)d_in[17];

    float* F = nullptr; int* I = nullptr;
    __nv_bfloat16* BH = nullptr; __nv_bfloat16* BL = nullptr;
    cudaGetSymbolAddress((void**)&F, g_f);
    cudaGetSymbolAddress((void**)&I, g_i);
    cudaGetSymbolAddress((void**)&BH, g_bh);
    cudaGetSymbolAddress((void**)&BL, g_bl);

    static bool attr_done = false;
    if (!attr_done) {
        cudaFuncSetAttribute(hgemm_nt<0>, cudaFuncAttributeMaxDynamicSharedMemorySize, SMEM_GEMM);
        cudaFuncSetAttribute(hgemm_nt<1>, cudaFuncAttributeMaxDynamicSharedMemorySize, SMEM_GEMM);
        cudaFuncSetAttribute(hgemm_nt<2>, cudaFuncAttributeMaxDynamicSharedMemorySize, SMEM_GEMM);
        attr_done = true;
    }

    float* qkv   = F + OFF_QKV;
    float* x1    = F + OFF_X1;
    float* h2f   = F + OFF_H2F;
    float* sdown = F + OFF_SDOWN;
    float* eob   = F + OFF_EO;
    float* probs = F + OFF_PROBS;
    float* topw  = F + OFF_TOPW;
    int* slot_tok = I + IOFF_SLOT;
    int* tok_slot = I + IOFF_TOKSLOT;
    int* topi     = I + IOFF_TOPI;
    int* cnt      = I + IOFF_CNT;

    float* outp = (float*)d_out;
    float* auxp = nullptr;
    float* xout = outp;
    if (out_size == TT * DD + 1) { auxp = outp; xout = outp + 1; }

    cudaMemsetAsync(cnt, 0, EE * sizeof(int));

    // 0) weight conversions (fp32 -> bf16 hi/lo planes)
    conv_kernel<<<(3 * DD * DD) / 1024, 256>>>(Wqkv, BH + BO_WQKV, BL + BO_WQKV, 3 * DD * DD);
    conv_kernel<<<(DD * DD) / 1024, 256>>>(Wo, BH + BO_WO, BL + BO_WO, DD * DD);
    conv_kernel<<<(EE * HIDD * DD) / 1024, 256>>>(We_up, BH + BO_WEUP, BL + BO_WEUP, EE * HIDD * DD);
    conv_kernel<<<(EE * DD * HIDD) / 1024, 256>>>(We_dn, BH + BO_WEDN, BL + BO_WEDN, EE * DD * HIDD);
    conv_kernel<<<(HIDD * DD) / 1024, 256>>>(Ws_up, BH + BO_WSUP, BL + BO_WSUP, HIDD * DD);
    conv_kernel<<<(DD * HIDD) / 1024, 256>>>(Ws_dn, BH + BO_WSDN, BL + BO_WSDN, DD * HIDD);

    // 1) LN1 -> bf16 planes
    ln_kernel<0><<<TT, 256>>>(x, ln1_g, ln1_b, nullptr, BH + BO_H, BL + BO_H);
    // 2) QKV projection
    hgemm_nt<0><<<dim3(24, 32, 1), 256, SMEM_GEMM>>>(
        BH + BO_H, BL + BO_H, BH + BO_WQKV, BL + BO_WQKV, bqkv, nullptr,
        qkv, nullptr, nullptr, TT, 3 * DD, DD, nullptr, nullptr, 0, 0, 0, 0, 0);
    // 3) causal attention -> bf16 planes
    attn_kernel<<<dim3(SS / 16, Bb * HH), 512>>>(qkv, BH + BO_ATTN, BL + BO_ATTN);
    // 4) output proj + residual -> x1 fp32
    hgemm_nt<2><<<dim3(8, 32, 1), 256, SMEM_GEMM>>>(
        BH + BO_ATTN, BL + BO_ATTN, BH + BO_WO, BL + BO_WO, bo, x,
        x1, nullptr, nullptr, TT, DD, DD, nullptr, nullptr, 0, 0, 0, 0, 0);
    // 5) LN2 -> fp32 (router) + bf16 planes
    ln_kernel<1><<<TT, 256>>>(x1, ln2_g, ln2_b, h2f, BH + BO_H2, BL + BO_H2);
    // 6) router
    router_kernel<<<TT, 128>>>(h2f, Wg, probs, topw, topi, slot_tok, tok_slot, cnt);
    // 7) aux loss
    if (auxp) aux_kernel<<<1, 512>>>(probs, topi, auxp);
    // 8) expert up (gathered, gelu -> bf16 planes)
    hgemm_nt<1><<<dim3(32, 32, 4), 256, SMEM_GEMM>>>(
        BH + BO_H2, BL + BO_H2, BH + BO_WEUP, BL + BO_WEUP, be_up, nullptr,
        nullptr, BH + BO_UPB, BL + BO_UPB, TT, HIDD, DD, slot_tok, cnt,
        0, (size_t)HIDD * DD, (size_t)HIDD, (size_t)TT * HIDD, (size_t)TT);
    // 9) expert down -> eob fp32
    hgemm_nt<0><<<dim3(8, 32, 4), 256, SMEM_GEMM>>>(
        BH + BO_UPB, BL + BO_UPB, BH + BO_WEDN, BL + BO_WEDN, be_dn, nullptr,
        eob, nullptr, nullptr, TT, DD, HIDD, nullptr, cnt,
        (size_t)TT * HIDD, (size_t)DD * HIDD, (size_t)DD, (size_t)TT * DD, 0);
    // 10) shared expert up (gelu -> bf16 planes)
    hgemm_nt<1><<<dim3(32, 32, 1), 256, SMEM_GEMM>>>(
        BH + BO_H2, BL + BO_H2, BH + BO_WSUP, BL + BO_WSUP, bs_up, nullptr,
        nullptr, BH + BO_SUP, BL + BO_SUP, TT, HIDD, DD, nullptr, nullptr, 0, 0, 0, 0, 0);
    // 11) shared expert down -> sdown fp32
    hgemm_nt<0><<<dim3(8, 32, 1), 256, SMEM_GEMM>>>(
        BH + BO_SUP, BL + BO_SUP, BH + BO_WSDN, BL + BO_WSDN, bs_dn, nullptr,
        sdown, nullptr, nullptr, TT, DD, HIDD, nullptr, nullptr, 0, 0, 0, 0, 0);
    // 12) combine
    combine_kernel<<<TT, 256>>>(x1, sdown, eob, topw, tok_slot, xout);
}

// round 10
// speedup vs baseline: 1.0847x; 1.0847x over previous
#include <cuda_runtime.h>
#include <cuda_bf16.h>
#include <math.h>
#include <stdint.h>

// ---------------- problem constants ----------------
#define Bb   2
#define SS   2048
#define DD   1024
#define HH   16
#define HDIM 64
#define EE   4
#define KSEL 2
#define HIDD 4096
#define TT   (Bb*SS)   // 4096 tokens

// ---------------- fp32 scratch ----------------
static const size_t OFF_QKV   = 0;                                   // TT*3*DD
static const size_t OFF_X1    = OFF_QKV   + (size_t)TT*3*DD;         // TT*DD
static const size_t OFF_H2F   = OFF_X1    + (size_t)TT*DD;           // TT*DD
static const size_t OFF_SDOWN = OFF_H2F   + (size_t)TT*DD;           // TT*DD
static const size_t OFF_EO    = OFF_SDOWN + (size_t)TT*DD;           // EE*TT*DD
static const size_t OFF_PROBS = OFF_EO    + (size_t)EE*TT*DD;        // TT*EE
static const size_t OFF_TOPW  = OFF_PROBS + (size_t)TT*EE;           // TT*KSEL
static const size_t F_TOTAL   = OFF_TOPW  + (size_t)TT*KSEL;
__device__ float g_f[F_TOTAL];

// ---------------- bf16 hi/lo planes ----------------
static const size_t BO_WQKV = 0;                                 // 3*DD*DD
static const size_t BO_WO   = BO_WQKV + (size_t)3*DD*DD;         // DD*DD
static const size_t BO_WEUP = BO_WO   + (size_t)DD*DD;           // EE*HIDD*DD
static const size_t BO_WEDN = BO_WEUP + (size_t)EE*HIDD*DD;      // EE*DD*HIDD
static const size_t BO_WSUP = BO_WEDN + (size_t)EE*DD*HIDD;      // HIDD*DD
static const size_t BO_WSDN = BO_WSUP + (size_t)HIDD*DD;         // DD*HIDD
static const size_t BO_H    = BO_WSDN + (size_t)DD*HIDD;         // TT*DD
static const size_t BO_ATTN = BO_H    + (size_t)TT*DD;           // TT*DD
static const size_t BO_H2   = BO_ATTN + (size_t)TT*DD;           // TT*DD
static const size_t BO_SUP  = BO_H2   + (size_t)TT*DD;           // TT*HIDD
static const size_t BO_UPB  = BO_SUP  + (size_t)TT*HIDD;         // EE*TT*HIDD
static const size_t B_TOTAL = BO_UPB  + (size_t)EE*TT*HIDD;
__device__ __nv_bfloat16 g_bh[B_TOTAL];
__device__ __nv_bfloat16 g_bl[B_TOTAL];

// ---------------- int scratch ----------------
static const size_t IOFF_SLOT    = 0;                       // EE*TT
static const size_t IOFF_TOKSLOT = IOFF_SLOT + EE*TT;       // TT*KSEL
static const size_t IOFF_TOPI    = IOFF_TOKSLOT + TT*KSEL;  // TT*KSEL
static const size_t IOFF_CNT     = IOFF_TOPI + TT*KSEL;     // EE
__device__ int g_i[IOFF_CNT + EE];

// ---------------- helpers ----------------
__device__ __forceinline__ float gelu_tanh(float x) {
    float z = 0.7978845608028654f * (x + 0.044715f * x * x * x);
    float e = __expf(2.f * z);
    float th = 1.f - 2.f / (e + 1.f);
    return 0.5f * x * (1.f + th);
}

__device__ __forceinline__ void mma_bf16(float* d, const uint32_t* a, const uint32_t* b) {
    asm volatile(
        "mma.sync.aligned.m16n8k16.row.col.f32.bf16.bf16.f32 "
        "{%0,%1,%2,%3}, {%4,%5,%6,%7}, {%8,%9}, {%0,%1,%2,%3};\n"
        : "+f"(d[0]), "+f"(d[1]), "+f"(d[2]), "+f"(d[3])
        : "r"(a[0]), "r"(a[1]), "r"(a[2]), "r"(a[3]), "r"(b[0]), "r"(b[1]));
}

__device__ __forceinline__ void ldsm4(uint32_t* r, uint32_t addr) {
    asm volatile("ldmatrix.sync.aligned.m8n8.x4.shared.b16 {%0,%1,%2,%3}, [%4];"
                 : "=r"(r[0]), "=r"(r[1]), "=r"(r[2]), "=r"(r[3]) : "r"(addr));
}

__device__ __forceinline__ void split2(float x, float y, uint32_t& hi, uint32_t& lo) {
    __nv_bfloat16 hx = __float2bfloat16_rn(x);
    __nv_bfloat16 hy = __float2bfloat16_rn(y);
    __nv_bfloat16 lx = __float2bfloat16_rn(x - __bfloat162float(hx));
    __nv_bfloat16 ly = __float2bfloat16_rn(y - __bfloat162float(hy));
    __nv_bfloat162 h2 = __nv_bfloat162(hx, hy);
    __nv_bfloat162 l2 = __nv_bfloat162(lx, ly);
    hi = *reinterpret_cast<uint32_t*>(&h2);
    lo = *reinterpret_cast<uint32_t*>(&l2);
}

__device__ __forceinline__ void cpa16(uint32_t dst, const void* src, int srcbytes) {
    asm volatile("cp.async.cg.shared.global [%0], [%1], 16, %2;"
                 :: "r"(dst), "l"(src), "r"(srcbytes));
}
__device__ __forceinline__ void cpa_commit() { asm volatile("cp.async.commit_group;"); }
__device__ __forceinline__ void cpa_wait_all() { asm volatile("cp.async.wait_group 0;"); }

// ---------------- fp32 -> bf16 hi/lo convert ----------------
__global__ void conv_kernel(const float* __restrict__ in, __nv_bfloat16* __restrict__ hi,
                            __nv_bfloat16* __restrict__ lo, int n) {
    int i = (blockIdx.x * blockDim.x + threadIdx.x) * 4;
    if (i >= n) return;
    float4 v = *(const float4*)(in + i);
    uint32_t h0, l0, h1, l1;
    split2(v.x, v.y, h0, l0);
    split2(v.z, v.w, h1, l1);
    *(uint32_t*)(hi + i)     = h0;
    *(uint32_t*)(hi + i + 2) = h1;
    *(uint32_t*)(lo + i)     = l0;
    *(uint32_t*)(lo + i + 2) = l1;
}

// ---------------- LayerNorm ----------------
template <int MODE>
__global__ void ln_kernel(const float* __restrict__ x, const float* __restrict__ g,
                          const float* __restrict__ b, float* __restrict__ outf,
                          __nv_bfloat16* __restrict__ ohi, __nv_bfloat16* __restrict__ olo) {
    int t = blockIdx.x, tid = threadIdx.x;
    const float* xr = x + (size_t)t * DD;
    float v[4], s = 0.f, sq = 0.f;
#pragma unroll
    for (int k = 0; k < 4; k++) {
        v[k] = xr[tid + k * 256];
        s += v[k]; sq += v[k] * v[k];
    }
    __shared__ float rs[256], rq[256];
    rs[tid] = s; rq[tid] = sq;
    __syncthreads();
    for (int o = 128; o > 0; o >>= 1) {
        if (tid < o) { rs[tid] += rs[tid + o]; rq[tid] += rq[tid + o]; }
        __syncthreads();
    }
    float mean = rs[0] * (1.f / DD);
    float var  = rq[0] * (1.f / DD) - mean * mean;
    float inv  = rsqrtf(var + 1e-5f);
#pragma unroll
    for (int k = 0; k < 4; k++) {
        int d = tid + k * 256;
        float val = (v[k] - mean) * inv * g[d] + b[d];
        if (MODE == 1) outf[(size_t)t * DD + d] = val;
        __nv_bfloat16 hx = __float2bfloat16_rn(val);
        __nv_bfloat16 lx = __float2bfloat16_rn(val - __bfloat162float(hx));
        ohi[(size_t)t * DD + d] = hx;
        olo[(size_t)t * DD + d] = lx;
    }
}

// ---------------- tensor-core NT GEMM, split-bf16 planes ----------------------
// C[M,N] = A[M,K]*Bw[N,K]^T + bias. Block 128x128, 4 warps of 64x64,
// k-tile 32, 2-stage cp.async. EPI: 0 fp32; 1 gelu->bf16 planes; 2 fp32+resid
#define LDAH 40            // smem row pitch in halves
#define ARR_B   10240      // one plane: 128 rows * 80B
#define STAGE_B 40960      // 4 planes
#define SMEM_GEMM 81920    // 2 stages
template <int EPI>
__global__ void __launch_bounds__(128) hgemm_nt(
    const __nv_bfloat16* __restrict__ Ahi, const __nv_bfloat16* __restrict__ Alo,
    const __nv_bfloat16* __restrict__ Bhi, const __nv_bfloat16* __restrict__ Blo,
    const float* __restrict__ bias, const float* __restrict__ resid,
    float* __restrict__ Cf, __nv_bfloat16* __restrict__ Chi, __nv_bfloat16* __restrict__ Clo,
    int M, int N, int Kd,
    const int* __restrict__ rowIdx, const int* __restrict__ cnt,
    size_t aZ, size_t bZ, size_t biasZ, size_t cZ, size_t idxZ) {
    int z = blockIdx.z;
    Ahi += (size_t)z * aZ; Alo += (size_t)z * aZ;
    Bhi += (size_t)z * bZ; Blo += (size_t)z * bZ;
    bias += (size_t)z * biasZ;
    if (EPI == 1) { Chi += (size_t)z * cZ; Clo += (size_t)z * cZ; }
    else          { Cf  += (size_t)z * cZ; }
    if (rowIdx) rowIdx += (size_t)z * idxZ;
    if (cnt) M = cnt[z];
    int mBase = blockIdx.y * 128;
    if (mBase >= M) return;
    int n0 = blockIdx.x * 128;

    extern __shared__ __align__(16) uint16_t smem_dyn[];
    uint32_t smemBase = (uint32_t)__cvta_generic_to_shared(smem_dyn);

    int tid = threadIdx.x;
    int wid = tid >> 5, lane = tid & 31;
    int warp_m = (wid & 1) * 64;
    int warp_n = (wid >> 1) * 64;

    // ---- cp.async mapping: seg i -> row (tid>>2)+32*i, 16B chunk (tid&3) ----
    ptrdiff_t dAlo = Alo - Ahi;
    ptrdiff_t dBlo = Blo - Bhi;
    int rowB0 = tid >> 2;
    int kh0   = (tid & 3) * 8;   // halves offset within k-tile
    const __nv_bfloat16* aHiP[4];
    int aOK[4];
    uint32_t sOff[4];
#pragma unroll
    for (int i = 0; i < 4; i++) {
        int row = rowB0 + 32 * i;
        sOff[i] = (uint32_t)(row * LDAH + kh0) * 2;
        int gmr = mBase + row;
        bool ok = gmr < M;
        int sr = ok ? (rowIdx ? rowIdx[gmr] : gmr) : 0;
        aHiP[i] = Ahi + (size_t)sr * Kd + kh0;
        aOK[i] = ok ? 16 : 0;
    }
    const __nv_bfloat16* bHi0 = Bhi + (size_t)(n0 + rowB0) * Kd + kh0;

    // ---- ldmatrix offsets ----
    uint32_t aOff[4];
#pragma unroll
    for (int mt = 0; mt < 4; mt++) {
        int row = warp_m + mt * 16 + (lane & 15);
        int colh = (lane >> 4) * 8;
        aOff[mt] = (uint32_t)(row * LDAH + colh) * 2;
    }
    uint32_t bOff[4];
#pragma unroll
    for (int np = 0; np < 4; np++) {
        int row = warp_n + np * 16 + (lane & 7) + ((lane >> 4) << 3);
        int colh = ((lane >> 3) & 1) * 8;
        bOff[np] = (uint32_t)(row * LDAH + colh) * 2;
    }

    float c[4][8][4];
#pragma unroll
    for (int i = 0; i < 4; i++)
#pragma unroll
        for (int j = 0; j < 8; j++)
#pragma unroll
            for (int k = 0; k < 4; k++) c[i][j][k] = 0.f;

    int nK = Kd >> 5;

    // prefetch stage 0
    {
        uint32_t sb = smemBase;
#pragma unroll
        for (int i = 0; i < 4; i++) {
            const __nv_bfloat16* bp = bHi0 + (size_t)(32 * i) * Kd;
            cpa16(sb + sOff[i],             aHiP[i], aOK[i]);
            cpa16(sb + ARR_B + sOff[i],     aHiP[i] + dAlo, aOK[i]);
            cpa16(sb + 2 * ARR_B + sOff[i], bp, 16);
            cpa16(sb + 3 * ARR_B + sOff[i], bp + dBlo, 16);
        }
        cpa_commit();
    }

    for (int kt = 0; kt < nK; kt++) {
        int cur = kt & 1;
        cpa_wait_all();
        __syncthreads();
        if (kt + 1 < nK) {
            uint32_t sb = smemBase + (cur ^ 1) * STAGE_B;
            int koff = (kt + 1) * 32;
#pragma unroll
            for (int i = 0; i < 4; i++) {
                const __nv_bfloat16* bp = bHi0 + (size_t)(32 * i) * Kd + koff;
                cpa16(sb + sOff[i],             aHiP[i] + koff, aOK[i]);
                cpa16(sb + ARR_B + sOff[i],     aHiP[i] + dAlo + koff, aOK[i]);
                cpa16(sb + 2 * ARR_B + sOff[i], bp, 16);
                cpa16(sb + 3 * ARR_B + sOff[i], bp + dBlo, 16);
            }
            cpa_commit();
        }
        uint32_t stageB = smemBase + cur * STAGE_B;
#pragma unroll
        for (int ks = 0; ks < 2; ks++) {
            uint32_t kb = ks * 32;
            uint32_t ah[4][4], al[4][4], bh[8][2], bl[8][2];
#pragma unroll
            for (int mt = 0; mt < 4; mt++) {
                ldsm4(ah[mt], stageB + aOff[mt] + kb);
                ldsm4(al[mt], stageB + ARR_B + aOff[mt] + kb);
            }
#pragma unroll
            for (int np = 0; np < 4; np++) {
                uint32_t r[4];
                ldsm4(r, stageB + 2 * ARR_B + bOff[np] + kb);
                bh[2 * np][0] = r[0]; bh[2 * np][1] = r[1];
                bh[2 * np + 1][0] = r[2]; bh[2 * np + 1][1] = r[3];
                ldsm4(r, stageB + 3 * ARR_B + bOff[np] + kb);
                bl[2 * np][0] = r[0]; bl[2 * np][1] = r[1];
                bl[2 * np + 1][0] = r[2]; bl[2 * np + 1][1] = r[3];
            }
#pragma unroll
            for (int mt = 0; mt < 4; mt++)
#pragma unroll
                for (int nt = 0; nt < 8; nt++) {
                    mma_bf16(c[mt][nt], ah[mt], bh[nt]);
                    mma_bf16(c[mt][nt], ah[mt], bl[nt]);
                    mma_bf16(c[mt][nt], al[mt], bh[nt]);
                }
        }
    }

    // ---- epilogue ----
#pragma unroll
    for (int mt = 0; mt < 4; mt++) {
#pragma unroll
        for (int nt = 0; nt < 8; nt++) {
            int col = n0 + warp_n + nt * 8 + (lane & 3) * 2;
            float2 bb = *(const float2*)(bias + col);
#pragma unroll
            for (int half = 0; half < 2; half++) {
                int r = mBase + warp_m + mt * 16 + (lane >> 2) + half * 8;
                if (r >= M) continue;
                float v0 = c[mt][nt][half * 2 + 0] + bb.x;
                float v1 = c[mt][nt][half * 2 + 1] + bb.y;
                if (EPI == 1) {
                    v0 = gelu_tanh(v0); v1 = gelu_tanh(v1);
                    uint32_t hi, lo;
                    split2(v0, v1, hi, lo);
                    *(uint32_t*)(Chi + (size_t)r * N + col) = hi;
                    *(uint32_t*)(Clo + (size_t)r * N + col) = lo;
                } else {
                    if (EPI == 2) {
                        float2 rr = *(const float2*)(resid + (size_t)r * N + col);
                        v0 += rr.x; v1 += rr.y;
                    }
                    *(float2*)(Cf + (size_t)r * N + col) = make_float2(v0, v1);
                }
            }
        }
    }
}

// ---------------- causal flash attention (bf16 hi/lo output) ------------------
__global__ void __launch_bounds__(512) attn_kernel(const float* __restrict__ qkv,
                                                   __nv_bfloat16* __restrict__ ohi,
                                                   __nv_bfloat16* __restrict__ olo) {
    __shared__ float q_s[16][64];
    __shared__ float k_s[32][65];
    __shared__ float v_s[32][64];
    int bh = blockIdx.y;
    int b = bh >> 4, h = bh & 15;
    int q0 = blockIdx.x * 16;
    int tid = threadIdx.x;
    int w = tid >> 5, lane = tid & 31;

    {
        int i = tid * 2;
        int qi = i >> 6, d = i & 63;
        const float* src = qkv + ((size_t)(b * SS + q0 + qi)) * (3 * DD) + h * 64 + d;
        float2 v = *(const float2*)src;
        q_s[qi][d]     = v.x * 0.125f;
        q_s[qi][d + 1] = v.y * 0.125f;
    }
    __syncthreads();
    float qr[64];
#pragma unroll
    for (int d = 0; d < 64; d++) qr[d] = q_s[w][d];

    int q = q0 + w;
    float M = -1e30f, L = 0.f, o0 = 0.f, o1 = 0.f;
    int nkeys = q0 + 16;

    for (int t0 = 0; t0 < nkeys; t0 += 32) {
        __syncthreads();
        {
            int r  = tid >> 4;
            int c4 = (tid & 15) * 4;
            int key = t0 + r;
            float4 kv = make_float4(0, 0, 0, 0), vv = make_float4(0, 0, 0, 0);
            if (key < SS) {
                size_t base = ((size_t)(b * SS + key)) * (3 * DD) + h * 64 + c4;
                kv = *(const float4*)(qkv + DD + base);
                vv = *(const float4*)(qkv + 2 * DD + base);
            }
            k_s[r][c4 + 0] = kv.x; k_s[r][c4 + 1] = kv.y;
            k_s[r][c4 + 2] = kv.z; k_s[r][c4 + 3] = kv.w;
            *(float4*)&v_s[r][c4] = vv;
        }
        __syncthreads();

        int key = t0 + lane;
        bool act = (key <= q);
        float s = -1e30f;
        if (act) {
            float a = 0.f;
#pragma unroll
            for (int d = 0; d < 64; d++) a += qr[d] * k_s[lane][d];
            s = a;
        }
        float mcur = s;
#pragma unroll
        for (int off = 16; off > 0; off >>= 1)
            mcur = fmaxf(mcur, __shfl_xor_sync(0xffffffffu, mcur, off));
        if (mcur > M) {
            float sc = __expf(M - mcur);
            o0 *= sc; o1 *= sc; L *= sc;
            M = mcur;
        }
        float p = act ? __expf(s - M) : 0.f;
        float ls = p;
#pragma unroll
        for (int off = 16; off > 0; off >>= 1)
            ls += __shfl_xor_sync(0xffffffffu, ls, off);
        L += ls;
#pragma unroll
        for (int j = 0; j < 32; j++) {
            float pj = __shfl_sync(0xffffffffu, p, j);
            float2 vv = *(const float2*)&v_s[j][lane * 2];
            o0 += pj * vv.x;
            o1 += pj * vv.y;
        }
    }
    float inv = 1.f / L;
    uint32_t hi, lo;
    split2(o0 * inv, o1 * inv, hi, lo);
    size_t off = ((size_t)(b * SS + q)) * DD + h * 64 + lane * 2;
    *(uint32_t*)(ohi + off) = hi;
    *(uint32_t*)(olo + off) = lo;
}

// ---------------- MoE router ----------------
__global__ void router_kernel(const float* __restrict__ h2, const float* __restrict__ Wg,
                              float* __restrict__ probs, float* __restrict__ topw,
                              int* __restrict__ topi, int* __restrict__ slot_tok,
                              int* __restrict__ tok_slot, int* __restrict__ cnt) {
    int t = blockIdx.x, tid = threadIdx.x;  // 128 threads
    const float* hr = h2 + (size_t)t * DD;
    float a0 = 0, a1 = 0, a2 = 0, a3 = 0;
    for (int d = tid; d < DD; d += 128) {
        float hv = hr[d];
        a0 += hv * Wg[d];
        a1 += hv * Wg[DD + d];
        a2 += hv * Wg[2 * DD + d];
        a3 += hv * Wg[3 * DD + d];
    }
    __shared__ float r[4][128];
    r[0][tid] = a0; r[1][tid] = a1; r[2][tid] = a2; r[3][tid] = a3;
    __syncthreads();
    for (int o = 64; o > 0; o >>= 1) {
        if (tid < o) {
#pragma unroll
            for (int e = 0; e < 4; e++) r[e][tid] += r[e][tid + o];
        }
        __syncthreads();
    }
    if (tid == 0) {
        float l[4] = {r[0][0], r[1][0], r[2][0], r[3][0]};
        float m = fmaxf(fmaxf(l[0], l[1]), fmaxf(l[2], l[3]));
        float p[4], sum = 0.f;
#pragma unroll
        for (int e = 0; e < 4; e++) { p[e] = __expf(l[e] - m); sum += p[e]; }
#pragma unroll
        for (int e = 0; e < 4; e++) { p[e] /= sum; probs[t * 4 + e] = p[e]; }
        int i0 = 0;
#pragma unroll
        for (int e = 1; e < 4; e++) if (p[e] > p[i0]) i0 = e;
        int i1 = -1;
#pragma unroll
        for (int e = 0; e < 4; e++)
            if (e != i0 && (i1 < 0 || p[e] > p[i1])) i1 = e;
        float w0 = p[i0], w1 = p[i1], ws = w0 + w1;
        w0 /= ws; w1 /= ws;
        int pos0 = atomicAdd(&cnt[i0], 1);
        slot_tok[i0 * TT + pos0] = t;
        tok_slot[t * 2]     = i0 * TT + pos0;
        int pos1 = atomicAdd(&cnt[i1], 1);
        slot_tok[i1 * TT + pos1] = t;
        tok_slot[t * 2 + 1] = i1 * TT + pos1;
        topw[t * 2] = w0; topw[t * 2 + 1] = w1;
        topi[t * 2] = i0; topi[t * 2 + 1] = i1;
    }
}

// ---------------- aux loss ----------------
__global__ void aux_kernel(const float* __restrict__ probs, const int* __restrict__ topi,
                           float* __restrict__ auxout) {
    int tid = threadIdx.x;  // 512
    float ps[4] = {0, 0, 0, 0};
    float cs[4] = {0, 0, 0, 0};
    for (int t = tid; t < TT; t += 512) {
#pragma unroll
        for (int e = 0; e < 4; e++) ps[e] += probs[t * 4 + e];
        cs[topi[t * 2]] += 1.f;
        cs[topi[t * 2 + 1]] += 1.f;
    }
    __shared__ float sp[4][512], sc[4][512];
#pragma unroll
    for (int e = 0; e < 4; e++) { sp[e][tid] = ps[e]; sc[e][tid] = cs[e]; }
    __syncthreads();
    for (int o = 256; o > 0; o >>= 1) {
        if (tid < o) {
#pragma unroll
            for (int e = 0; e < 4; e++) {
                sp[e][tid] += sp[e][tid + o];
                sc[e][tid] += sc[e][tid + o];
            }
        }
        __syncthreads();
    }
    if (tid == 0) {
        float aux = 0.f;
#pragma unroll
        for (int e = 0; e < 4; e++) {
            float fi = sc[e][0] / (float)(TT * KSEL);
            float Pi = sp[e][0] / (float)TT;
            aux += fi * Pi;
        }
        auxout[0] = 0.01f * (float)EE * aux;
    }
}

// ---------------- final combine (scalar stores) ----------------
__global__ void combine_kernel(const float* __restrict__ x1, const float* __restrict__ sdown,
                               const float* __restrict__ eo, const float* __restrict__ topw,
                               const int* __restrict__ tok_slot, float* __restrict__ xout) {
    int t = blockIdx.x, tid = threadIdx.x;
    int c = tid * 4;
    int s0 = tok_slot[t * 2], s1 = tok_slot[t * 2 + 1];
    float w0 = topw[t * 2], w1 = topw[t * 2 + 1];
    float4 a  = *(const float4*)(x1 + (size_t)t * DD + c);
    float4 sd = *(const float4*)(sdown + (size_t)t * DD + c);
    float4 e0 = *(const float4*)(eo + (size_t)s0 * DD + c);
    float4 e1 = *(const float4*)(eo + (size_t)s1 * DD + c);
    float* o = xout + (size_t)t * DD + c;
    o[0] = a.x + sd.x + w0 * e0.x + w1 * e1.x;
    o[1] = a.y + sd.y + w0 * e0.y + w1 * e1.y;
    o[2] = a.z + sd.z + w0 * e0.z + w1 * e1.z;
    o[3] = a.w + sd.w + w0 * e0.w + w1 * e1.w;
}

// ---------------- launch ------------------------------------------------------
extern "C" void kernel_launch(void* const* d_in, const int* in_sizes, int n_in,
                              void* d_out, int out_size) {
    const float* x      = (const float*)d_in[0];
    const float* ln1_g  = (const float*)d_in[1];
    const float* ln1_b  = (const float*)d_in[2];
    const float* Wqkv   = (const float*)d_in[3];
    const float* bqkv   = (const float*)d_in[4];
    const float* Wo     = (const float*)d_in[5];
    const float* bo     = (const float*)d_in[6];
    const float* ln2_g  = (const float*)d_in[7];
    const float* ln2_b  = (const float*)d_in[8];
    const float* Wg     = (const float*)d_in[9];
    const float* We_up  = (const float*)d_in[10];
    const float* be_up  = (const float*)d_in[11];
    const float* We_dn  = (const float*)d_in[12];
    const float* be_dn  = (const float*)d_in[13];
    const float* Ws_up  = (const float*)d_in[14];
    const float* bs_up  = (const float*)d_in[15];
    const float* Ws_dn  = (const float*)d_in[16];
    const float* bs_dn  = (const float*)d_in[17];

    float* F = nullptr; int* I = nullptr;
    __nv_bfloat16* BH = nullptr; __nv_bfloat16* BL = nullptr;
    cudaGetSymbolAddress((void**)&F, g_f);
    cudaGetSymbolAddress((void**)&I, g_i);
    cudaGetSymbolAddress((void**)&BH, g_bh);
    cudaGetSymbolAddress((void**)&BL, g_bl);

    static bool attr_done = false;
    if (!attr_done) {
        cudaFuncSetAttribute(hgemm_nt<0>, cudaFuncAttributeMaxDynamicSharedMemorySize, SMEM_GEMM);
        cudaFuncSetAttribute(hgemm_nt<1>, cudaFuncAttributeMaxDynamicSharedMemorySize, SMEM_GEMM);
        cudaFuncSetAttribute(hgemm_nt<2>, cudaFuncAttributeMaxDynamicSharedMemorySize, SMEM_GEMM);
        attr_done = true;
    }

    float* qkv   = F + OFF_QKV;
    float* x1    = F + OFF_X1;
    float* h2f   = F + OFF_H2F;
    float* sdown = F + OFF_SDOWN;
    float* eob   = F + OFF_EO;
    float* probs = F + OFF_PROBS;
    float* topw  = F + OFF_TOPW;
    int* slot_tok = I + IOFF_SLOT;
    int* tok_slot = I + IOFF_TOKSLOT;
    int* topi     = I + IOFF_TOPI;
    int* cnt      = I + IOFF_CNT;

    float* outp = (float*)d_out;
    float* auxp = nullptr;
    float* xout = outp;
    if (out_size == TT * DD + 1) { auxp = outp; xout = outp + 1; }

    cudaMemsetAsync(cnt, 0, EE * sizeof(int));

    // 0) weight conversions
    conv_kernel<<<(3 * DD * DD) / 1024, 256>>>(Wqkv, BH + BO_WQKV, BL + BO_WQKV, 3 * DD * DD);
    conv_kernel<<<(DD * DD) / 1024, 256>>>(Wo, BH + BO_WO, BL + BO_WO, DD * DD);
    conv_kernel<<<(EE * HIDD * DD) / 1024, 256>>>(We_up, BH + BO_WEUP, BL + BO_WEUP, EE * HIDD * DD);
    conv_kernel<<<(EE * DD * HIDD) / 1024, 256>>>(We_dn, BH + BO_WEDN, BL + BO_WEDN, EE * DD * HIDD);
    conv_kernel<<<(HIDD * DD) / 1024, 256>>>(Ws_up, BH + BO_WSUP, BL + BO_WSUP, HIDD * DD);
    conv_kernel<<<(DD * HIDD) / 1024, 256>>>(Ws_dn, BH + BO_WSDN, BL + BO_WSDN, DD * HIDD);

    // 1) LN1 -> bf16 planes
    ln_kernel<0><<<TT, 256>>>(x, ln1_g, ln1_b, nullptr, BH + BO_H, BL + BO_H);
    // 2) QKV projection
    hgemm_nt<0><<<dim3(24, 32, 1), 128, SMEM_GEMM>>>(
        BH + BO_H, BL + BO_H, BH + BO_WQKV, BL + BO_WQKV, bqkv, nullptr,
        qkv, nullptr, nullptr, TT, 3 * DD, DD, nullptr, nullptr, 0, 0, 0, 0, 0);
    // 3) causal attention -> bf16 planes
    attn_kernel<<<dim3(SS / 16, Bb * HH), 512>>>(qkv, BH + BO_ATTN, BL + BO_ATTN);
    // 4) output proj + residual -> x1 fp32
    hgemm_nt<2><<<dim3(8, 32, 1), 128, SMEM_GEMM>>>(
        BH + BO_ATTN, BL + BO_ATTN, BH + BO_WO, BL + BO_WO, bo, x,
        x1, nullptr, nullptr, TT, DD, DD, nullptr, nullptr, 0, 0, 0, 0, 0);
    // 5) LN2 -> fp32 + bf16 planes
    ln_kernel<1><<<TT, 256>>>(x1, ln2_g, ln2_b, h2f, BH + BO_H2, BL + BO_H2);
    // 6) router
    router_kernel<<<TT, 128>>>(h2f, Wg, probs, topw, topi, slot_tok, tok_slot, cnt);
    // 7) aux loss
    if (auxp) aux_kernel<<<1, 512>>>(probs, topi, auxp);
    // 8) expert up (gathered, gelu -> bf16 planes)
    hgemm_nt<1><<<dim3(32, 32, 4), 128, SMEM_GEMM>>>(
        BH + BO_H2, BL + BO_H2, BH + BO_WEUP, BL + BO_WEUP, be_up, nullptr,
        nullptr, BH + BO_UPB, BL + BO_UPB, TT, HIDD, DD, slot_tok, cnt,
        0, (size_t)HIDD * DD, (size_t)HIDD, (size_t)TT * HIDD, (size_t)TT);
    // 9) expert down -> eob fp32
    hgemm_nt<0><<<dim3(8, 32, 4), 128, SMEM_GEMM>>>(
        BH + BO_UPB, BL + BO_UPB, BH + BO_WEDN, BL + BO_WEDN, be_dn, nullptr,
        eob, nullptr, nullptr, TT, DD, HIDD, nullptr, cnt,
        (size_t)TT * HIDD, (size_t)DD * HIDD, (size_t)DD, (size_t)TT * DD, 0);
    // 10) shared expert up (gelu -> bf16 planes)
    hgemm_nt<1><<<dim3(32, 32, 1), 128, SMEM_GEMM>>>(
        BH + BO_H2, BL + BO_H2, BH + BO_WSUP, BL + BO_WSUP, bs_up, nullptr,
        nullptr, BH + BO_SUP, BL + BO_SUP, TT, HIDD, DD, nullptr, nullptr, 0, 0, 0, 0, 0);
    // 11) shared expert down -> sdown fp32
    hgemm_nt<0><<<dim3(8, 32, 1), 128, SMEM_GEMM>>>(
        BH + BO_SUP, BL + BO_SUP, BH + BO_WSDN, BL + BO_WSDN, bs_dn, nullptr,
        sdown, nullptr, nullptr, TT, DD, HIDD, nullptr, nullptr, 0, 0, 0, 0, 0);
    // 12) combine
    combine_kernel<<<TT, 256>>>(x1, sdown, eob, topw, tok_slot, xout);
}